// round 2
// baseline (speedup 1.0000x reference)
#include <cuda_runtime.h>
#include <math.h>

// ContrastiveLoss: N=16384, D=128
//   sq_dists[i][j] = max(sq1[i] + sq2[j] - 2*dot(Tx1[i],Tx2[j]), 0)
//   repulsion[i]   = mean_j exp(-sq_dists[i][j])        (2*TAU = 1.0)
//   attraction[i]  = exp(-||Tx1[i]-Tx2[i]||^2)
//   out = [ mean_i log1p(rep_i/(att_i+1e-8)), mean(att), mean(rep) ]
//
// exp(-x) == 0 in fp32 for x >= ~104 (denormal floor). For N(0,1) data,
// sq_dists ~ 256 +- 32, so almost all terms underflow to exactly 0.
// Epilogue: per-thread min(sq) filter, rare exact expf path.

#define D   128
#define BM  128
#define BN  128
#define BK  16
#define NMAX 16384
#define GT_MAX (NMAX / BN)   // 128 column tiles
#define SQ_CUT 105.0f        // expf(-x) == 0 for x >= 104; margin

// ---- static device scratch (no allocations allowed) ----
__device__ float  g_sq1[NMAX];
__device__ float  g_sq2[NMAX];
__device__ float  g_possq[NMAX];
__device__ float  g_part[(size_t)GT_MAX * NMAX];  // [col_tile][row] partial row sums
__device__ double g_blk[NMAX / 256][3];           // per-block triple partials

// ---- packed f32x2 helpers (Blackwell) ----
__device__ __forceinline__ unsigned long long pack2(float lo, float hi) {
    unsigned long long r;
    asm("mov.b64 %0, {%1, %2};" : "=l"(r) : "f"(lo), "f"(hi));
    return r;
}
__device__ __forceinline__ void unpack2(unsigned long long v, float &lo, float &hi) {
    asm("mov.b64 {%0, %1}, %2;" : "=f"(lo), "=f"(hi) : "l"(v));
}
__device__ __forceinline__ void ffma2(unsigned long long &d,
                                      unsigned long long a,
                                      unsigned long long b) {
    asm("fma.rn.f32x2 %0, %1, %2, %0;" : "+l"(d) : "l"(a), "l"(b));
}

// ============================================================================
// Kernel 0: per-row squared norms of Tx1, Tx2 and ||Tx1[i]-Tx2[i]||^2.
// One warp per row; 128 floats = 32 lanes x float4.
// ============================================================================
__global__ void prep_kernel(const float* __restrict__ x1,
                            const float* __restrict__ x2, int n) {
    int warp = (blockIdx.x * blockDim.x + threadIdx.x) >> 5;
    int lane = threadIdx.x & 31;
    if (warp >= n) return;
    float4 va = reinterpret_cast<const float4*>(x1 + (size_t)warp * D)[lane];
    float4 vb = reinterpret_cast<const float4*>(x2 + (size_t)warp * D)[lane];
    float s1 = va.x*va.x + va.y*va.y + va.z*va.z + va.w*va.w;
    float s2 = vb.x*vb.x + vb.y*vb.y + vb.z*vb.z + vb.w*vb.w;
    float dx = va.x - vb.x, dy = va.y - vb.y, dz = va.z - vb.z, dw = va.w - vb.w;
    float sp = dx*dx + dy*dy + dz*dz + dw*dw;
    #pragma unroll
    for (int o = 16; o; o >>= 1) {
        s1 += __shfl_xor_sync(0xffffffffu, s1, o);
        s2 += __shfl_xor_sync(0xffffffffu, s2, o);
        sp += __shfl_xor_sync(0xffffffffu, sp, o);
    }
    if (lane == 0) {
        g_sq1[warp]   = s1;
        g_sq2[warp]   = s2;
        g_possq[warp] = sp;
    }
}

// ============================================================================
// Kernel 1: fused 128x128 tile GEMM (A*B^T, K=128) + exp epilogue + row sums.
// 256 threads, 8x8 microtile, f32x2 packed FMA, double-buffered SMEM.
// Writes deterministic per-(col_tile,row) partials (no atomics).
// ============================================================================
__global__ void __launch_bounds__(256, 2)
tile_kernel(const float* __restrict__ A, const float* __restrict__ B, int n) {
    __shared__ float As[2][BK][BM + 4];
    __shared__ float Bs[2][BK][BN + 4];

    const int tid = threadIdx.x;
    const int tx  = tid & 15;   // column group (8 cols each)
    const int ty  = tid >> 4;   // row group (8 rows each)
    const int i0  = blockIdx.y * BM;
    const int j0  = blockIdx.x * BN;

    // staging mapping: 256 threads load a 128x16 tile (2 rows apart by 64)
    const int lr = tid >> 2;            // 0..63
    const int lc = (tid & 3) * 4;       // 0,4,8,12

    const float* Ag = A + (size_t)(i0 + lr) * D + lc;
    const float* Bg = B + (size_t)(j0 + lr) * D + lc;

    unsigned long long acc[8][4];
    #pragma unroll
    for (int m = 0; m < 8; m++)
        #pragma unroll
        for (int p = 0; p < 4; p++) acc[m][p] = 0ull;

    float4 ra0, ra1, rb0, rb1;
    ra0 = *reinterpret_cast<const float4*>(Ag);
    ra1 = *reinterpret_cast<const float4*>(Ag + 64 * D);
    rb0 = *reinterpret_cast<const float4*>(Bg);
    rb1 = *reinterpret_cast<const float4*>(Bg + 64 * D);

    int buf = 0;
    // stage tile 0
    {
        As[0][lc+0][lr] = ra0.x; As[0][lc+1][lr] = ra0.y;
        As[0][lc+2][lr] = ra0.z; As[0][lc+3][lr] = ra0.w;
        As[0][lc+0][lr+64] = ra1.x; As[0][lc+1][lr+64] = ra1.y;
        As[0][lc+2][lr+64] = ra1.z; As[0][lc+3][lr+64] = ra1.w;
        Bs[0][lc+0][lr] = rb0.x; Bs[0][lc+1][lr] = rb0.y;
        Bs[0][lc+2][lr] = rb0.z; Bs[0][lc+3][lr] = rb0.w;
        Bs[0][lc+0][lr+64] = rb1.x; Bs[0][lc+1][lr+64] = rb1.y;
        Bs[0][lc+2][lr+64] = rb1.z; Bs[0][lc+3][lr+64] = rb1.w;
    }
    __syncthreads();

    #pragma unroll 1
    for (int kt = 0; kt < D / BK; kt++) {
        if (kt + 1 < D / BK) {
            const float* Agn = Ag + (kt + 1) * BK;
            const float* Bgn = Bg + (kt + 1) * BK;
            ra0 = *reinterpret_cast<const float4*>(Agn);
            ra1 = *reinterpret_cast<const float4*>(Agn + 64 * D);
            rb0 = *reinterpret_cast<const float4*>(Bgn);
            rb1 = *reinterpret_cast<const float4*>(Bgn + 64 * D);
        }
        #pragma unroll
        for (int k = 0; k < BK; k++) {
            float4 a0 = *reinterpret_cast<const float4*>(&As[buf][k][ty * 8]);
            float4 a1 = *reinterpret_cast<const float4*>(&As[buf][k][ty * 8 + 4]);
            ulonglong2 b0 = *reinterpret_cast<const ulonglong2*>(&Bs[buf][k][tx * 8]);
            ulonglong2 b1 = *reinterpret_cast<const ulonglong2*>(&Bs[buf][k][tx * 8 + 4]);
            unsigned long long ap[8];
            ap[0] = pack2(a0.x, a0.x); ap[1] = pack2(a0.y, a0.y);
            ap[2] = pack2(a0.z, a0.z); ap[3] = pack2(a0.w, a0.w);
            ap[4] = pack2(a1.x, a1.x); ap[5] = pack2(a1.y, a1.y);
            ap[6] = pack2(a1.z, a1.z); ap[7] = pack2(a1.w, a1.w);
            unsigned long long bp[4] = { b0.x, b0.y, b1.x, b1.y };
            #pragma unroll
            for (int m = 0; m < 8; m++)
                #pragma unroll
                for (int p = 0; p < 4; p++)
                    ffma2(acc[m][p], ap[m], bp[p]);
        }
        if (kt + 1 < D / BK) {
            int nb = buf ^ 1;
            As[nb][lc+0][lr] = ra0.x; As[nb][lc+1][lr] = ra0.y;
            As[nb][lc+2][lr] = ra0.z; As[nb][lc+3][lr] = ra0.w;
            As[nb][lc+0][lr+64] = ra1.x; As[nb][lc+1][lr+64] = ra1.y;
            As[nb][lc+2][lr+64] = ra1.z; As[nb][lc+3][lr+64] = ra1.w;
            Bs[nb][lc+0][lr] = rb0.x; Bs[nb][lc+1][lr] = rb0.y;
            Bs[nb][lc+2][lr] = rb0.z; Bs[nb][lc+3][lr] = rb0.w;
            Bs[nb][lc+0][lr+64] = rb1.x; Bs[nb][lc+1][lr+64] = rb1.y;
            Bs[nb][lc+2][lr+64] = rb1.z; Bs[nb][lc+3][lr+64] = rb1.w;
            __syncthreads();
            buf = nb;
        }
    }

    // ---- epilogue: sq_dist, underflow filter, rare exp, row partial sums ----
    float s1r[8], s2c[8];
    #pragma unroll
    for (int m = 0; m < 8; m++) s1r[m] = g_sq1[i0 + ty * 8 + m];
    #pragma unroll
    for (int q = 0; q < 8; q++) s2c[q] = g_sq2[j0 + tx * 8 + q];

    float rsum[8];
    #pragma unroll
    for (int m = 0; m < 8; m++) rsum[m] = 0.0f;

    float minsq = 1e30f;
    #pragma unroll
    for (int m = 0; m < 8; m++) {
        #pragma unroll
        for (int p = 0; p < 4; p++) {
            float lo, hi;
            unpack2(acc[m][p], lo, hi);
            float sqa = fmaf(-2.0f, lo, s1r[m] + s2c[2*p]);
            float sqb = fmaf(-2.0f, hi, s1r[m] + s2c[2*p+1]);
            minsq = fminf(minsq, fminf(sqa, sqb));
        }
    }
    if (minsq < SQ_CUT) {   // ~3% of threads on this data; correctness-exact
        #pragma unroll
        for (int m = 0; m < 8; m++) {
            #pragma unroll
            for (int p = 0; p < 4; p++) {
                float lo, hi;
                unpack2(acc[m][p], lo, hi);
                float sqa = fmaf(-2.0f, lo, s1r[m] + s2c[2*p]);
                float sqb = fmaf(-2.0f, hi, s1r[m] + s2c[2*p+1]);
                if (sqa < SQ_CUT) rsum[m] += expf(-fmaxf(sqa, 0.0f));
                if (sqb < SQ_CUT) rsum[m] += expf(-fmaxf(sqb, 0.0f));
            }
        }
    }

    // reduce across the 16 column-group lanes (same ty shares rows);
    // tid = ty*16+tx -> 16-lane segments within a warp
    #pragma unroll
    for (int m = 0; m < 8; m++) {
        #pragma unroll
        for (int o = 8; o; o >>= 1)
            rsum[m] += __shfl_down_sync(0xffffffffu, rsum[m], o, 16);
    }
    if (tx == 0) {
        #pragma unroll
        for (int m = 0; m < 8; m++)
            g_part[(size_t)blockIdx.x * n + i0 + ty * 8 + m] = rsum[m];
    }
}

// ============================================================================
// Kernel 2: per-row finalize + per-block triple reduction (double accum).
// ============================================================================
__global__ void finalize_kernel(int n, int gtiles) {
    int i = blockIdx.x * blockDim.x + threadIdx.x;
    float s = 0.0f;
    for (int g = 0; g < gtiles; g++) s += g_part[(size_t)g * n + i];
    float rep  = s / (float)n;                  // n is a power of two: exact scale
    float att  = expf(-g_possq[i]);
    float li   = log1pf(rep / (att + 1e-8f));

    double v0 = (double)li, v1 = (double)att, v2 = (double)rep;
    #pragma unroll
    for (int o = 16; o; o >>= 1) {
        v0 += __shfl_down_sync(0xffffffffu, v0, o);
        v1 += __shfl_down_sync(0xffffffffu, v1, o);
        v2 += __shfl_down_sync(0xffffffffu, v2, o);
    }
    __shared__ double sm[3][8];
    int lane = threadIdx.x & 31, w = threadIdx.x >> 5;
    if (lane == 0) { sm[0][w] = v0; sm[1][w] = v1; sm[2][w] = v2; }
    __syncthreads();
    if (threadIdx.x == 0) {
        double t0 = 0, t1 = 0, t2 = 0;
        #pragma unroll
        for (int q = 0; q < 8; q++) { t0 += sm[0][q]; t1 += sm[1][q]; t2 += sm[2][q]; }
        g_blk[blockIdx.x][0] = t0;
        g_blk[blockIdx.x][1] = t1;
        g_blk[blockIdx.x][2] = t2;
    }
}

// ============================================================================
// Kernel 3: final deterministic reduce -> out[0..2]
// ============================================================================
__global__ void output_kernel(float* __restrict__ out, int n, int nb, int out_size) {
    if (threadIdx.x == 0) {
        double t0 = 0, t1 = 0, t2 = 0;
        for (int b = 0; b < nb; b++) {
            t0 += g_blk[b][0]; t1 += g_blk[b][1]; t2 += g_blk[b][2];
        }
        if (out_size > 0) out[0] = (float)(t0 / (double)n);
        if (out_size > 1) out[1] = (float)(t1 / (double)n);
        if (out_size > 2) out[2] = (float)(t2 / (double)n);
    }
}

extern "C" void kernel_launch(void* const* d_in, const int* in_sizes, int n_in,
                              void* d_out, int out_size) {
    const float* x1 = (const float*)d_in[0];
    const float* x2 = (const float*)d_in[1];
    int n = in_sizes[0] / D;          // 16384
    int gtiles = n / BN;              // 128

    prep_kernel<<<(n * 32 + 255) / 256, 256>>>(x1, x2, n);

    dim3 grid(gtiles, n / BM);
    tile_kernel<<<grid, 256>>>(x1, x2, n);

    finalize_kernel<<<n / 256, 256>>>(n, gtiles);
    output_kernel<<<1, 32>>>((float*)d_out, n, n / 256, out_size);
}

// round 4
// speedup vs baseline: 4.2013x; 4.2013x over previous
#include <cuda_runtime.h>
#include <cuda_bf16.h>
#include <math.h>
#include <stdint.h>

// ContrastiveLoss: N=16384, D=128.
// sq[i][j] = max(sq1[i]+sq2[j]-2*dot, 0); exp(-sq)==0 in fp32 for sq>~104.
// bf16 mma.sync GEMM as a coarse filter (EST_CUT=118 margin), exact fp32
// recompute for the (essentially never occurring) near pairs.
// NOTE: harness PTX target is plain sm_100 -> tcgen05 unavailable; use
// baseline-PTX mma.sync.m16n8k16.bf16 (HMMA) instead.

#define D    128
#define BM   128
#define BN   128
#define NMAX 16384
#define GT_MAX (NMAX / BN)
#define SQ_CUT  105.0f
#define EST_CUT 118.0f

// ---- static device scratch ----
__device__ float         g_sq1[NMAX];
__device__ float         g_sq2[NMAX];
__device__ float         g_possq[NMAX];
__device__ __nv_bfloat16 g_a16[(size_t)NMAX * D];
__device__ __nv_bfloat16 g_b16[(size_t)NMAX * D];
__device__ float         g_part[(size_t)GT_MAX * NMAX];
__device__ double        g_blk[NMAX / 256][3];

// ---- SMEM layout (dynamic): padded rows, 272B stride (conflict-free ldmatrix)
#define ROWB      272
#define SMEM_A    0
#define SMEM_B    (128 * ROWB)            // 34816
#define SMEM_PART (2 * 128 * ROWB)        // 69632: float[4][128]
#define SMEM_H    (SMEM_PART + 2048)      // 71680: float[128] (sq2 for tile)
#define SMEM_TOTAL (SMEM_H + 512 + 64)

__device__ __forceinline__ uint32_t smem_u32(const void* p) {
    uint32_t a;
    asm("{ .reg .u64 t; cvta.to.shared.u64 t, %1; cvt.u32.u64 %0, t; }"
        : "=r"(a) : "l"(p));
    return a;
}
__device__ __forceinline__ void ldsm4(uint32_t* r, uint32_t addr) {
    asm volatile("ldmatrix.sync.aligned.m8n8.x4.shared.b16 {%0,%1,%2,%3}, [%4];"
                 : "=r"(r[0]), "=r"(r[1]), "=r"(r[2]), "=r"(r[3]) : "r"(addr));
}
__device__ __forceinline__ void ldsm2(uint32_t* r, uint32_t addr) {
    asm volatile("ldmatrix.sync.aligned.m8n8.x2.shared.b16 {%0,%1}, [%2];"
                 : "=r"(r[0]), "=r"(r[1]) : "r"(addr));
}
__device__ __forceinline__ void mma16816(float* d, const uint32_t* a, const uint32_t* b) {
    asm volatile(
        "mma.sync.aligned.m16n8k16.row.col.f32.bf16.bf16.f32 "
        "{%0,%1,%2,%3}, {%4,%5,%6,%7}, {%8,%9}, {%0,%1,%2,%3};"
        : "+f"(d[0]), "+f"(d[1]), "+f"(d[2]), "+f"(d[3])
        : "r"(a[0]), "r"(a[1]), "r"(a[2]), "r"(a[3]), "r"(b[0]), "r"(b[1]));
}

// ============================================================================
// Kernel 0: row norms, pos_sq, bf16 conversion. One warp per row.
// ============================================================================
__global__ void prep_kernel(const float* __restrict__ x1,
                            const float* __restrict__ x2, int n) {
    int warp = (blockIdx.x * blockDim.x + threadIdx.x) >> 5;
    int lane = threadIdx.x & 31;
    if (warp >= n) return;
    float4 va = reinterpret_cast<const float4*>(x1 + (size_t)warp * D)[lane];
    float4 vb = reinterpret_cast<const float4*>(x2 + (size_t)warp * D)[lane];

    __nv_bfloat162* pa = reinterpret_cast<__nv_bfloat162*>(g_a16 + (size_t)warp * D + lane * 4);
    __nv_bfloat162* pb = reinterpret_cast<__nv_bfloat162*>(g_b16 + (size_t)warp * D + lane * 4);
    pa[0] = __floats2bfloat162_rn(va.x, va.y);
    pa[1] = __floats2bfloat162_rn(va.z, va.w);
    pb[0] = __floats2bfloat162_rn(vb.x, vb.y);
    pb[1] = __floats2bfloat162_rn(vb.z, vb.w);

    float s1 = va.x*va.x + va.y*va.y + va.z*va.z + va.w*va.w;
    float s2 = vb.x*vb.x + vb.y*vb.y + vb.z*vb.z + vb.w*vb.w;
    float dx = va.x - vb.x, dy = va.y - vb.y, dz = va.z - vb.z, dw = va.w - vb.w;
    float sp = dx*dx + dy*dy + dz*dz + dw*dw;
    #pragma unroll
    for (int o = 16; o; o >>= 1) {
        s1 += __shfl_xor_sync(0xffffffffu, s1, o);
        s2 += __shfl_xor_sync(0xffffffffu, s2, o);
        sp += __shfl_xor_sync(0xffffffffu, sp, o);
    }
    if (lane == 0) { g_sq1[warp] = s1; g_sq2[warp] = s2; g_possq[warp] = sp; }
}

// ============================================================================
// Kernel 1: bf16 HMMA tile (M=128, N=128, K=128) + filter epilogue.
// 256 threads = 8 warps (2 warp-rows x 4 warp-cols), warp tile 64x32.
// ============================================================================
__global__ void __launch_bounds__(256, 2)
tile_kernel(const float* __restrict__ X1, const float* __restrict__ X2, int n) {
    extern __shared__ char smem[];
    const int tid  = threadIdx.x;
    const int l    = tid & 31;
    const int w    = tid >> 5;
    const int wrow = w >> 2;      // 0..1, 64 M-rows each
    const int wcol = w & 3;       // 0..3, 32 N-cols each
    const int i0   = blockIdx.y * BM;
    const int j0   = blockIdx.x * BN;

    // ---- stage A (128x128 bf16) and B (128x128 bf16), padded rows ----
    #pragma unroll
    for (int it = 0; it < 8; it++) {
        int idx = tid + it * 256;            // 0..2047
        int row = idx >> 4, ch = idx & 15;
        uint4 va = *reinterpret_cast<const uint4*>(
            reinterpret_cast<const char*>(g_a16) + (size_t)(i0 + row) * 256 + ch * 16);
        *reinterpret_cast<uint4*>(smem + SMEM_A + row * ROWB + ch * 16) = va;
        uint4 vb = *reinterpret_cast<const uint4*>(
            reinterpret_cast<const char*>(g_b16) + (size_t)(j0 + row) * 256 + ch * 16);
        *reinterpret_cast<uint4*>(smem + SMEM_B + row * ROWB + ch * 16) = vb;
    }
    if (tid < 128)
        reinterpret_cast<float*>(smem + SMEM_H)[tid] = g_sq2[j0 + tid];
    __syncthreads();

    const uint32_t sbase = smem_u32(smem);
    // ldmatrix lane addresses (standard m16n8k16 fragment mapping)
    const uint32_t a_addr = sbase + SMEM_A
        + (uint32_t)(wrow * 64 + (l & 7) + ((l >> 3) & 1) * 8) * ROWB
        + ((l >> 4) & 1) * 16;
    const uint32_t b_addr = sbase + SMEM_B
        + (uint32_t)(wcol * 32 + (l & 7)) * ROWB
        + ((l >> 3) & 1) * 16;

    float acc[4][4][4];
    #pragma unroll
    for (int mt = 0; mt < 4; mt++)
        #pragma unroll
        for (int nt = 0; nt < 4; nt++)
            #pragma unroll
            for (int e = 0; e < 4; e++) acc[mt][nt][e] = 0.0f;

    #pragma unroll
    for (int ks = 0; ks < 8; ks++) {
        uint32_t a[4][4], b[4][2];
        #pragma unroll
        for (int mt = 0; mt < 4; mt++)
            ldsm4(a[mt], a_addr + mt * 16 * ROWB + ks * 32);
        #pragma unroll
        for (int nt = 0; nt < 4; nt++)
            ldsm2(b[nt], b_addr + nt * 8 * ROWB + ks * 32);
        #pragma unroll
        for (int mt = 0; mt < 4; mt++)
            #pragma unroll
            for (int nt = 0; nt < 4; nt++)
                mma16816(acc[mt][nt], a[mt], b[nt]);
    }

    // ---- epilogue: filter + rare exact recompute + row sums ----
    // D fragment: thread l owns rows mt*16 + (l>>2) and +8 (local to warp-row
    // block), cols nt*8 + (l&3)*2 + {0,1} (local to warp-col block).
    const float* hs = reinterpret_cast<const float*>(smem + SMEM_H);
    float s1a[4], s1b[4];
    #pragma unroll
    for (int mt = 0; mt < 4; mt++) {
        int r = wrow * 64 + mt * 16 + (l >> 2);
        s1a[mt] = g_sq1[i0 + r];
        s1b[mt] = g_sq1[i0 + r + 8];
    }
    float s2c[8];
    #pragma unroll
    for (int nt = 0; nt < 4; nt++) {
        s2c[nt*2]   = hs[wcol * 32 + nt * 8 + (l & 3) * 2];
        s2c[nt*2+1] = hs[wcol * 32 + nt * 8 + (l & 3) * 2 + 1];
    }

    float minsq = 1e30f;
    #pragma unroll
    for (int mt = 0; mt < 4; mt++)
        #pragma unroll
        for (int nt = 0; nt < 4; nt++) {
            float q0 = fmaf(-2.0f, acc[mt][nt][0], s1a[mt] + s2c[nt*2]);
            float q1 = fmaf(-2.0f, acc[mt][nt][1], s1a[mt] + s2c[nt*2+1]);
            float q2 = fmaf(-2.0f, acc[mt][nt][2], s1b[mt] + s2c[nt*2]);
            float q3 = fmaf(-2.0f, acc[mt][nt][3], s1b[mt] + s2c[nt*2+1]);
            minsq = fminf(minsq, fminf(fminf(q0, q1), fminf(q2, q3)));
        }

    float rsA[4], rsB[4];
    #pragma unroll
    for (int mt = 0; mt < 4; mt++) { rsA[mt] = 0.0f; rsB[mt] = 0.0f; }

    if (minsq < EST_CUT) {   // essentially never on this data; exactness path
        #pragma unroll 1
        for (int mt = 0; mt < 4; mt++) {
            int iA = i0 + wrow * 64 + mt * 16 + (l >> 2);
            int iB = iA + 8;
            #pragma unroll 1
            for (int nt = 0; nt < 4; nt++) {
                #pragma unroll
                for (int e = 0; e < 4; e++) {
                    float s1v = (e < 2) ? s1a[mt] : s1b[mt];
                    float s2v = s2c[nt*2 + (e & 1)];
                    float est = fmaf(-2.0f, acc[mt][nt][e], s1v + s2v);
                    if (est < EST_CUT) {
                        int i = (e < 2) ? iA : iB;
                        int j = j0 + wcol * 32 + nt * 8 + (l & 3) * 2 + (e & 1);
                        const float* xr = X1 + (size_t)i * D;
                        const float* yr = X2 + (size_t)j * D;
                        float dot = 0.0f;
                        #pragma unroll 8
                        for (int k = 0; k < D; k++) dot = fmaf(xr[k], yr[k], dot);
                        float sq = fmaxf(s1v + s2v - 2.0f * dot, 0.0f);
                        if (sq < SQ_CUT) {
                            float v = expf(-sq);
                            if (e < 2) rsA[mt] += v; else rsB[mt] += v;
                        }
                    }
                }
            }
        }
    }

    // reduce over the 4 lanes that share each row (lanes xor 1, xor 2)
    float* part = reinterpret_cast<float*>(smem + SMEM_PART);
    #pragma unroll
    for (int mt = 0; mt < 4; mt++) {
        rsA[mt] += __shfl_xor_sync(0xffffffffu, rsA[mt], 1);
        rsA[mt] += __shfl_xor_sync(0xffffffffu, rsA[mt], 2);
        rsB[mt] += __shfl_xor_sync(0xffffffffu, rsB[mt], 1);
        rsB[mt] += __shfl_xor_sync(0xffffffffu, rsB[mt], 2);
        if ((l & 3) == 0) {
            int r = wrow * 64 + mt * 16 + (l >> 2);
            part[wcol * 128 + r]     = rsA[mt];
            part[wcol * 128 + r + 8] = rsB[mt];
        }
    }
    __syncthreads();
    if (tid < 128) {
        float s = part[tid] + part[128 + tid] + part[256 + tid] + part[384 + tid];
        g_part[(size_t)blockIdx.x * n + i0 + tid] = s;
    }
}

// ============================================================================
// Kernel 2: per-row finalize + per-block triple reduction (double accum).
// ============================================================================
__global__ void finalize_kernel(int n, int gtiles) {
    int i = blockIdx.x * blockDim.x + threadIdx.x;
    float s = 0.0f;
    for (int g = 0; g < gtiles; g++) s += g_part[(size_t)g * n + i];
    float rep = s / (float)n;
    float att = expf(-g_possq[i]);
    float li  = log1pf(rep / (att + 1e-8f));

    double v0 = (double)li, v1 = (double)att, v2 = (double)rep;
    #pragma unroll
    for (int o = 16; o; o >>= 1) {
        v0 += __shfl_down_sync(0xffffffffu, v0, o);
        v1 += __shfl_down_sync(0xffffffffu, v1, o);
        v2 += __shfl_down_sync(0xffffffffu, v2, o);
    }
    __shared__ double sm[3][8];
    int lane = threadIdx.x & 31, w = threadIdx.x >> 5;
    if (lane == 0) { sm[0][w] = v0; sm[1][w] = v1; sm[2][w] = v2; }
    __syncthreads();
    if (threadIdx.x == 0) {
        double t0 = 0, t1 = 0, t2 = 0;
        #pragma unroll
        for (int q = 0; q < 8; q++) { t0 += sm[0][q]; t1 += sm[1][q]; t2 += sm[2][q]; }
        g_blk[blockIdx.x][0] = t0;
        g_blk[blockIdx.x][1] = t1;
        g_blk[blockIdx.x][2] = t2;
    }
}

__global__ void output_kernel(float* __restrict__ out, int n, int nb, int out_size) {
    if (threadIdx.x == 0) {
        double t0 = 0, t1 = 0, t2 = 0;
        for (int b = 0; b < nb; b++) {
            t0 += g_blk[b][0]; t1 += g_blk[b][1]; t2 += g_blk[b][2];
        }
        if (out_size > 0) out[0] = (float)(t0 / (double)n);
        if (out_size > 1) out[1] = (float)(t1 / (double)n);
        if (out_size > 2) out[2] = (float)(t2 / (double)n);
    }
}

extern "C" void kernel_launch(void* const* d_in, const int* in_sizes, int n_in,
                              void* d_out, int out_size) {
    const float* x1 = (const float*)d_in[0];
    const float* x2 = (const float*)d_in[1];
    int n = in_sizes[0] / D;              // 16384
    int gtiles = n / BN;                  // 128

    cudaFuncSetAttribute(tile_kernel,
                         cudaFuncAttributeMaxDynamicSharedMemorySize, SMEM_TOTAL);

    prep_kernel<<<(n * 32 + 255) / 256, 256>>>(x1, x2, n);

    dim3 grid(gtiles, n / BM);            // (128, 128)
    tile_kernel<<<grid, 256, SMEM_TOTAL>>>(x1, x2, n);

    finalize_kernel<<<n / 256, 256>>>(n, gtiles);
    output_kernel<<<1, 32>>>((float*)d_out, n, n / 256, out_size);
}

// round 5
// speedup vs baseline: 5.4848x; 1.3055x over previous
#include <cuda_runtime.h>
#include <cuda_bf16.h>
#include <math.h>
#include <stdint.h>

// ContrastiveLoss: N=16384, D=128.
// sq[i][j] = max(sq1[i]+sq2[j]-2*dot, 0); exp(-sq)==0 in fp32 for sq>~104.
// int8 mma.sync (m16n8k32.s8) GEMM as a coarse filter: q = round(20*x),
// dot ~= (s32 dot)/400, worst-case sq error < 14 -> EST_CUT=119 margin.
// Exact fp32 recompute for the (essentially never occurring) near pairs.
// Rows with any |20*x| > 127 (prob ~1e-3 over the whole dataset) get a
// -1e9 bias on their filtered norm, forcing the exact path -> still exact.

#define D    128
#define BM   128
#define BN   128
#define NMAX 16384
#define GT_MAX (NMAX / BN)
#define SQ_CUT  105.0f
#define EST_CUT 119.0f
#define QS      20.0f        // quant scale
#define INV2S2  0.005f       // 2 / (QS*QS)

// ---- static device scratch ----
__device__ float  g_sq1[NMAX];     // clean |x1_i|^2
__device__ float  g_sq2[NMAX];     // clean |x2_j|^2
__device__ float  g_f1[NMAX];      // sq1 - (dirty ? 1e9 : 0)   (filter copy)
__device__ float  g_f2[NMAX];
__device__ float  g_possq[NMAX];
__device__ char   g_a8[(size_t)NMAX * D];
__device__ char   g_b8[(size_t)NMAX * D];
__device__ float  g_part[(size_t)GT_MAX * NMAX];
__device__ double g_blk[NMAX / 256][3];

// ---- SMEM layout: padded int8 rows, 144B stride (conflict-free ldmatrix) --
#define ROWB       144
#define SMEM_A     0
#define SMEM_B     (128 * ROWB)              // 18432
#define SMEM_PART  (2 * 128 * ROWB)          // 36864: float[4][128]
#define SMEM_H     (SMEM_PART + 2048)        // 38912: float[128] filtered sq2
#define SMEM_TOTAL (SMEM_H + 512 + 64)

__device__ __forceinline__ uint32_t smem_u32(const void* p) {
    uint32_t a;
    asm("{ .reg .u64 t; cvta.to.shared.u64 t, %1; cvt.u32.u64 %0, t; }"
        : "=r"(a) : "l"(p));
    return a;
}
__device__ __forceinline__ void ldsm4(uint32_t* r, uint32_t addr) {
    asm volatile("ldmatrix.sync.aligned.m8n8.x4.shared.b16 {%0,%1,%2,%3}, [%4];"
                 : "=r"(r[0]), "=r"(r[1]), "=r"(r[2]), "=r"(r[3]) : "r"(addr));
}
__device__ __forceinline__ void ldsm2(uint32_t* r, uint32_t addr) {
    asm volatile("ldmatrix.sync.aligned.m8n8.x2.shared.b16 {%0,%1}, [%2];"
                 : "=r"(r[0]), "=r"(r[1]) : "r"(addr));
}
__device__ __forceinline__ void imma16832(int* d, const uint32_t* a, const uint32_t* b) {
    asm volatile(
        "mma.sync.aligned.m16n8k32.row.col.s32.s8.s8.s32 "
        "{%0,%1,%2,%3}, {%4,%5,%6,%7}, {%8,%9}, {%0,%1,%2,%3};"
        : "+r"(d[0]), "+r"(d[1]), "+r"(d[2]), "+r"(d[3])
        : "r"(a[0]), "r"(a[1]), "r"(a[2]), "r"(a[3]), "r"(b[0]), "r"(b[1]));
}

__device__ __forceinline__ int quant1(float x, float& mx) {
    float f = x * QS;
    mx = fmaxf(mx, fabsf(f));
    f = fmaxf(fminf(f, 127.0f), -127.0f);
    return __float2int_rn(f);
}

// ============================================================================
// Kernel 0: row norms, pos_sq, int8 quantization + dirty flags. 1 warp/row.
// ============================================================================
__global__ void prep_kernel(const float* __restrict__ x1,
                            const float* __restrict__ x2, int n) {
    int warp = (blockIdx.x * blockDim.x + threadIdx.x) >> 5;
    int lane = threadIdx.x & 31;
    if (warp >= n) return;
    float4 va = reinterpret_cast<const float4*>(x1 + (size_t)warp * D)[lane];
    float4 vb = reinterpret_cast<const float4*>(x2 + (size_t)warp * D)[lane];

    float mxa = 0.0f, mxb = 0.0f;
    char4 qa, qb;
    qa.x = (char)quant1(va.x, mxa); qa.y = (char)quant1(va.y, mxa);
    qa.z = (char)quant1(va.z, mxa); qa.w = (char)quant1(va.w, mxa);
    qb.x = (char)quant1(vb.x, mxb); qb.y = (char)quant1(vb.y, mxb);
    qb.z = (char)quant1(vb.z, mxb); qb.w = (char)quant1(vb.w, mxb);
    reinterpret_cast<char4*>(g_a8 + (size_t)warp * D)[lane] = qa;
    reinterpret_cast<char4*>(g_b8 + (size_t)warp * D)[lane] = qb;

    unsigned dirtyA = __ballot_sync(0xffffffffu, mxa > 127.0f);
    unsigned dirtyB = __ballot_sync(0xffffffffu, mxb > 127.0f);

    float s1 = va.x*va.x + va.y*va.y + va.z*va.z + va.w*va.w;
    float s2 = vb.x*vb.x + vb.y*vb.y + vb.z*vb.z + vb.w*vb.w;
    float dx = va.x - vb.x, dy = va.y - vb.y, dz = va.z - vb.z, dw = va.w - vb.w;
    float sp = dx*dx + dy*dy + dz*dz + dw*dw;
    #pragma unroll
    for (int o = 16; o; o >>= 1) {
        s1 += __shfl_xor_sync(0xffffffffu, s1, o);
        s2 += __shfl_xor_sync(0xffffffffu, s2, o);
        sp += __shfl_xor_sync(0xffffffffu, sp, o);
    }
    if (lane == 0) {
        g_sq1[warp] = s1;
        g_sq2[warp] = s2;
        g_f1[warp]  = s1 - (dirtyA ? 1e9f : 0.0f);
        g_f2[warp]  = s2 - (dirtyB ? 1e9f : 0.0f);
        g_possq[warp] = sp;
    }
}

// ============================================================================
// Kernel 1: int8 IMMA tile (M=128, N=128, K=128) + filter epilogue.
// 256 threads = 8 warps (2 warp-rows x 4 warp-cols), warp tile 64x32.
// ============================================================================
__global__ void __launch_bounds__(256, 2)
tile_kernel(const float* __restrict__ X1, const float* __restrict__ X2, int n) {
    extern __shared__ char smem[];
    const int tid  = threadIdx.x;
    const int l    = tid & 31;
    const int w    = tid >> 5;
    const int wrow = w >> 2;      // 0..1, 64 M-rows each
    const int wcol = w & 3;       // 0..3, 32 N-cols each
    const int i0   = blockIdx.y * BM;
    const int j0   = blockIdx.x * BN;

    // ---- stage A (128x128 s8) and B (128x128 s8), padded rows ----
    #pragma unroll
    for (int it = 0; it < 4; it++) {
        int idx = tid + it * 256;            // 0..1023 chunks of 16B
        int row = idx >> 3, ch = idx & 7;
        uint4 va = *reinterpret_cast<const uint4*>(
            g_a8 + (size_t)(i0 + row) * 128 + ch * 16);
        *reinterpret_cast<uint4*>(smem + SMEM_A + row * ROWB + ch * 16) = va;
        uint4 vb = *reinterpret_cast<const uint4*>(
            g_b8 + (size_t)(j0 + row) * 128 + ch * 16);
        *reinterpret_cast<uint4*>(smem + SMEM_B + row * ROWB + ch * 16) = vb;
    }
    if (tid < 128)
        reinterpret_cast<float*>(smem + SMEM_H)[tid] = g_f2[j0 + tid];
    __syncthreads();

    const uint32_t sbase = smem_u32(smem);
    // ldmatrix lane addresses (m16n8k32 s8 fragments; byte layout == the
    // bf16 m16n8k16 pattern, 32B per k-step)
    const uint32_t a_addr = sbase + SMEM_A
        + (uint32_t)(wrow * 64 + (l & 7) + ((l >> 3) & 1) * 8) * ROWB
        + ((l >> 4) & 1) * 16;
    const uint32_t b_addr = sbase + SMEM_B
        + (uint32_t)(wcol * 32 + (l & 7)) * ROWB
        + ((l >> 3) & 1) * 16;

    int acc[4][4][4];
    #pragma unroll
    for (int mt = 0; mt < 4; mt++)
        #pragma unroll
        for (int nt = 0; nt < 4; nt++)
            #pragma unroll
            for (int e = 0; e < 4; e++) acc[mt][nt][e] = 0;

    #pragma unroll
    for (int ks = 0; ks < 4; ks++) {          // k32 per step
        uint32_t a[4][4], b[4][2];
        #pragma unroll
        for (int mt = 0; mt < 4; mt++)
            ldsm4(a[mt], a_addr + mt * 16 * ROWB + ks * 32);
        #pragma unroll
        for (int nt = 0; nt < 4; nt++)
            ldsm2(b[nt], b_addr + nt * 8 * ROWB + ks * 32);
        #pragma unroll
        for (int mt = 0; mt < 4; mt++)
            #pragma unroll
            for (int nt = 0; nt < 4; nt++)
                imma16832(acc[mt][nt], a[mt], b[nt]);
    }

    // ---- epilogue: filtered est, rare exact recompute, row sums ----
    // D frag: thread l owns rows mt*16 + (l>>2) / +8, cols nt*8 + (l&3)*2 +{0,1}
    const float* hs = reinterpret_cast<const float*>(smem + SMEM_H);
    float s1a[4], s1b[4];
    #pragma unroll
    for (int mt = 0; mt < 4; mt++) {
        int r = wrow * 64 + mt * 16 + (l >> 2);
        s1a[mt] = g_f1[i0 + r];
        s1b[mt] = g_f1[i0 + r + 8];
    }
    float s2c[8];
    #pragma unroll
    for (int nt = 0; nt < 4; nt++) {
        s2c[nt*2]   = hs[wcol * 32 + nt * 8 + (l & 3) * 2];
        s2c[nt*2+1] = hs[wcol * 32 + nt * 8 + (l & 3) * 2 + 1];
    }

    float minsq = 1e30f;
    #pragma unroll
    for (int mt = 0; mt < 4; mt++)
        #pragma unroll
        for (int nt = 0; nt < 4; nt++) {
            float q0 = fmaf(-INV2S2, (float)acc[mt][nt][0], s1a[mt] + s2c[nt*2]);
            float q1 = fmaf(-INV2S2, (float)acc[mt][nt][1], s1a[mt] + s2c[nt*2+1]);
            float q2 = fmaf(-INV2S2, (float)acc[mt][nt][2], s1b[mt] + s2c[nt*2]);
            float q3 = fmaf(-INV2S2, (float)acc[mt][nt][3], s1b[mt] + s2c[nt*2+1]);
            minsq = fminf(minsq, fminf(fminf(q0, q1), fminf(q2, q3)));
        }

    float rsA[4], rsB[4];
    #pragma unroll
    for (int mt = 0; mt < 4; mt++) { rsA[mt] = 0.0f; rsB[mt] = 0.0f; }

    if (minsq < EST_CUT) {   // essentially never; exactness path
        #pragma unroll 1
        for (int mt = 0; mt < 4; mt++) {
            int iA = i0 + wrow * 64 + mt * 16 + (l >> 2);
            int iB = iA + 8;
            #pragma unroll 1
            for (int nt = 0; nt < 4; nt++) {
                #pragma unroll
                for (int e = 0; e < 4; e++) {
                    float s1v = (e < 2) ? s1a[mt] : s1b[mt];
                    float s2v = s2c[nt*2 + (e & 1)];
                    float est = fmaf(-INV2S2, (float)acc[mt][nt][e], s1v + s2v);
                    if (est < EST_CUT) {
                        int i = (e < 2) ? iA : iB;
                        int j = j0 + wcol * 32 + nt * 8 + (l & 3) * 2 + (e & 1);
                        const float* xr = X1 + (size_t)i * D;
                        const float* yr = X2 + (size_t)j * D;
                        float dot = 0.0f;
                        #pragma unroll 8
                        for (int k = 0; k < D; k++) dot = fmaf(xr[k], yr[k], dot);
                        float sq = fmaxf(g_sq1[i] + g_sq2[j] - 2.0f * dot, 0.0f);
                        if (sq < SQ_CUT) {
                            float v = expf(-sq);
                            if (e < 2) rsA[mt] += v; else rsB[mt] += v;
                        }
                    }
                }
            }
        }
    }

    // reduce over the 4 lanes that share each row
    float* part = reinterpret_cast<float*>(smem + SMEM_PART);
    #pragma unroll
    for (int mt = 0; mt < 4; mt++) {
        rsA[mt] += __shfl_xor_sync(0xffffffffu, rsA[mt], 1);
        rsA[mt] += __shfl_xor_sync(0xffffffffu, rsA[mt], 2);
        rsB[mt] += __shfl_xor_sync(0xffffffffu, rsB[mt], 1);
        rsB[mt] += __shfl_xor_sync(0xffffffffu, rsB[mt], 2);
        if ((l & 3) == 0) {
            int r = wrow * 64 + mt * 16 + (l >> 2);
            part[wcol * 128 + r]     = rsA[mt];
            part[wcol * 128 + r + 8] = rsB[mt];
        }
    }
    __syncthreads();
    if (tid < 128) {
        float s = part[tid] + part[128 + tid] + part[256 + tid] + part[384 + tid];
        g_part[(size_t)blockIdx.x * n + i0 + tid] = s;
    }
}

// ============================================================================
// Kernel 2: per-row finalize + per-block triple reduction (double accum).
// ============================================================================
__global__ void finalize_kernel(int n, int gtiles) {
    int i = blockIdx.x * blockDim.x + threadIdx.x;
    float s = 0.0f;
    for (int g = 0; g < gtiles; g++) s += g_part[(size_t)g * n + i];
    float rep = s / (float)n;
    float att = expf(-g_possq[i]);
    float li  = log1pf(rep / (att + 1e-8f));

    double v0 = (double)li, v1 = (double)att, v2 = (double)rep;
    #pragma unroll
    for (int o = 16; o; o >>= 1) {
        v0 += __shfl_down_sync(0xffffffffu, v0, o);
        v1 += __shfl_down_sync(0xffffffffu, v1, o);
        v2 += __shfl_down_sync(0xffffffffu, v2, o);
    }
    __shared__ double sm[3][8];
    int lane = threadIdx.x & 31, w = threadIdx.x >> 5;
    if (lane == 0) { sm[0][w] = v0; sm[1][w] = v1; sm[2][w] = v2; }
    __syncthreads();
    if (threadIdx.x == 0) {
        double t0 = 0, t1 = 0, t2 = 0;
        #pragma unroll
        for (int q = 0; q < 8; q++) { t0 += sm[0][q]; t1 += sm[1][q]; t2 += sm[2][q]; }
        g_blk[blockIdx.x][0] = t0;
        g_blk[blockIdx.x][1] = t1;
        g_blk[blockIdx.x][2] = t2;
    }
}

// ============================================================================
// Kernel 3: parallel final reduce (64 threads; nb = 64).
// ============================================================================
__global__ void output_kernel(float* __restrict__ out, int n, int nb, int out_size) {
    int t = threadIdx.x;
    double v0 = 0, v1 = 0, v2 = 0;
    if (t < nb) { v0 = g_blk[t][0]; v1 = g_blk[t][1]; v2 = g_blk[t][2]; }
    #pragma unroll
    for (int o = 16; o; o >>= 1) {
        v0 += __shfl_down_sync(0xffffffffu, v0, o);
        v1 += __shfl_down_sync(0xffffffffu, v1, o);
        v2 += __shfl_down_sync(0xffffffffu, v2, o);
    }
    __shared__ double sm[3][2];
    int lane = t & 31, w = t >> 5;
    if (lane == 0) { sm[0][w] = v0; sm[1][w] = v1; sm[2][w] = v2; }
    __syncthreads();
    if (t == 0) {
        double t0 = sm[0][0] + sm[0][1];
        double t1 = sm[1][0] + sm[1][1];
        double t2 = sm[2][0] + sm[2][1];
        if (out_size > 0) out[0] = (float)(t0 / (double)n);
        if (out_size > 1) out[1] = (float)(t1 / (double)n);
        if (out_size > 2) out[2] = (float)(t2 / (double)n);
    }
}

extern "C" void kernel_launch(void* const* d_in, const int* in_sizes, int n_in,
                              void* d_out, int out_size) {
    const float* x1 = (const float*)d_in[0];
    const float* x2 = (const float*)d_in[1];
    int n = in_sizes[0] / D;              // 16384
    int gtiles = n / BN;                  // 128

    cudaFuncSetAttribute(tile_kernel,
                         cudaFuncAttributeMaxDynamicSharedMemorySize, SMEM_TOTAL);

    prep_kernel<<<(n * 32 + 255) / 256, 256>>>(x1, x2, n);

    dim3 grid(gtiles, n / BM);            // (128, 128)
    tile_kernel<<<grid, 256, SMEM_TOTAL>>>(x1, x2, n);

    finalize_kernel<<<n / 256, 256>>>(n, gtiles);
    output_kernel<<<1, 64>>>((float*)d_out, n, n / 256, out_size);
}